// round 3
// baseline (speedup 1.0000x reference)
#include <cuda_runtime.h>
#include <cuda_bf16.h>
#include <cstdint>

#define DEVINL __device__ __forceinline__

// ---------------- problem constants ----------------
constexpr int Sc = 2048, Dc = 64, BHc = 32;
constexpr int NKT = Sc / 128;                 // 16 k-tiles
constexpr int QKD = BHc * Sc * Dc;            // 4194304
constexpr int MASKW = Sc * Sc / 32;           // 131072
constexpr long long OUT_ELEMS  = (long long)QKD;
constexpr long long ATTN_ELEMS = (long long)BHc * Sc * Sc;

// ---------------- static device scratch ----------------
__device__ __nv_bfloat16 g_Qhi[QKD], g_Qlo[QKD], g_Khi[QKD], g_Klo[QKD];
__device__ __nv_bfloat16 g_Vthi[QKD], g_Vtlo[QKD];   // transposed: [bh][d][s]
__device__ unsigned g_maskbits[MASKW];

// ---------------- smem layout (padded rows, conflict-free LDS) -------------
constexpr int KROW = 144;                    // 64 bf16 (128B) + 16B pad
constexpr int VROW = 272;                    // 128 bf16 (256B) + 16B pad
constexpr int OFF_KHI = 0;
constexpr int OFF_KLO = 128 * KROW;          // 18432
constexpr int OFF_VHI = 2 * 128 * KROW;      // 36864
constexpr int OFF_VLO = OFF_VHI + 64 * VROW; // +17408
constexpr int SMEM_BYTES = OFF_VLO + 64 * VROW;  // 71680

// ---------------- mma helpers ----------------
DEVINL void mma16816(float c[4], const uint32_t a[4], uint32_t b0, uint32_t b1) {
    asm volatile(
        "mma.sync.aligned.m16n8k16.row.col.f32.bf16.bf16.f32 "
        "{%0,%1,%2,%3}, {%4,%5,%6,%7}, {%8,%9}, {%0,%1,%2,%3};"
        : "+f"(c[0]), "+f"(c[1]), "+f"(c[2]), "+f"(c[3])
        : "r"(a[0]), "r"(a[1]), "r"(a[2]), "r"(a[3]), "r"(b0), "r"(b1));
}
DEVINL uint32_t pk2(float x, float y) {
    __nv_bfloat162 t = __floats2bfloat162_rn(x, y);
    return *(uint32_t*)&t;   // x in low half
}

// ---------------- preprocessing ----------------
__global__ void conv_qk_kernel(const float* __restrict__ q, const float* __restrict__ k) {
    int i = blockIdx.x * 256 + threadIdx.x;
    float qv = q[i];
    __nv_bfloat16 qh = __float2bfloat16(qv);
    g_Qhi[i] = qh;
    g_Qlo[i] = __float2bfloat16(qv - __bfloat162float(qh));
    float kv = k[i];
    __nv_bfloat16 kh = __float2bfloat16(kv);
    g_Khi[i] = kh;
    g_Klo[i] = __float2bfloat16(kv - __bfloat162float(kh));
}

// tiled transpose v[bh,s,d] -> g_Vt[bh,d,s] hi/lo
__global__ void conv_v_kernel(const float* __restrict__ v) {
    __shared__ float tile[64][65];
    int bh = blockIdx.x >> 5;
    int s0 = (blockIdx.x & 31) * 64;
    int tid = threadIdx.x;
    for (int i = tid; i < 64 * 64; i += 256) {
        int sr = i >> 6, dc = i & 63;
        tile[sr][dc] = v[((long long)bh * Sc + s0 + sr) * Dc + dc];
    }
    __syncthreads();
    for (int i = tid; i < 64 * 64; i += 256) {
        int dr = i >> 6, sc = i & 63;
        float vv = tile[sc][dr];
        __nv_bfloat16 vh = __float2bfloat16(vv);
        long long gi = ((long long)bh * Dc + dr) * Sc + s0 + sc;
        g_Vthi[gi] = vh;
        g_Vtlo[gi] = __float2bfloat16(vv - __bfloat162float(vh));
    }
}

__global__ void pack_mask_kernel(const int* __restrict__ m) {
    int i = blockIdx.x * 256 + threadIdx.x;     // row = i>>6, word = i&63
    int row = i >> 6, w = i & 63;
    const int4* p = (const int4*)(m + (long long)row * Sc + w * 32);
    unsigned bits = 0;
    #pragma unroll
    for (int g = 0; g < 8; ++g) {
        int4 x = p[g];
        bits |= (unsigned)(x.x != 0) << (g * 4 + 0);
        bits |= (unsigned)(x.y != 0) << (g * 4 + 1);
        bits |= (unsigned)(x.z != 0) << (g * 4 + 2);
        bits |= (unsigned)(x.w != 0) << (g * 4 + 3);
    }
    g_maskbits[i] = bits;
}

// ---------------- tile loaders (gmem -> padded smem) ----------------
DEVINL void load_k_tiles(char* smem, int bh, int kt, int tid) {
    const uint4* kh = (const uint4*)g_Khi + ((long long)bh * Sc + kt * 128) * 8;
    const uint4* kl = (const uint4*)g_Klo + ((long long)bh * Sc + kt * 128) * 8;
    #pragma unroll
    for (int i = tid; i < 128 * 8; i += 256) {
        int r = i >> 3, w = i & 7;
        int off = r * KROW + w * 16;
        *(uint4*)(smem + OFF_KHI + off) = kh[i];
        *(uint4*)(smem + OFF_KLO + off) = kl[i];
    }
}
DEVINL void load_v_tiles(char* smem, int bh, int kt, int tid) {
    const uint4* vh = (const uint4*)g_Vthi;
    const uint4* vl = (const uint4*)g_Vtlo;
    #pragma unroll
    for (int i = tid; i < 64 * 16; i += 256) {
        int d = i >> 4, w = i & 15;
        int off = d * VROW + w * 16;
        long long gi = ((long long)bh * 64 + d) * 256 + kt * 16 + w;
        *(uint4*)(smem + OFF_VHI + off) = vh[gi];
        *(uint4*)(smem + OFF_VLO + off) = vl[gi];
    }
}

// ---------------- main fused kernel ----------------
__global__ void __launch_bounds__(256, 1)
attn_main_kernel(float* __restrict__ out, float* __restrict__ attn) {
    extern __shared__ __align__(16) char smem[];
    const int qt = blockIdx.x;             // 0..15
    const int bh = blockIdx.y;             // 0..31
    const int tid = threadIdx.x;
    const int wid = tid >> 5, lane = tid & 31;
    const int gid = lane >> 2, tig = lane & 3;
    const int r0 = wid * 16 + gid;         // q-row (block-local), second row r0+8
    const long long qrow0 = (long long)qt * 128 + r0;

    // ---- stage Q tile into K region, pull A-fragments to registers ----
    {
        const uint4* qh = (const uint4*)g_Qhi + ((long long)bh * Sc + qt * 128) * 8;
        const uint4* ql = (const uint4*)g_Qlo + ((long long)bh * Sc + qt * 128) * 8;
        #pragma unroll
        for (int i = tid; i < 128 * 8; i += 256) {
            int r = i >> 3, w = i & 7;
            int off = r * KROW + w * 16;
            *(uint4*)(smem + OFF_KHI + off) = qh[i];
            *(uint4*)(smem + OFF_KLO + off) = ql[i];
        }
    }
    __syncthreads();
    uint32_t qfh[4][4], qfl[4][4];
    #pragma unroll
    for (int kk = 0; kk < 4; ++kk) {
        int base = r0 * KROW + (kk * 16 + 2 * tig) * 2;
        qfh[kk][0] = *(const uint32_t*)(smem + OFF_KHI + base);
        qfh[kk][1] = *(const uint32_t*)(smem + OFF_KHI + base + 8 * KROW);
        qfh[kk][2] = *(const uint32_t*)(smem + OFF_KHI + base + 16);
        qfh[kk][3] = *(const uint32_t*)(smem + OFF_KHI + base + 8 * KROW + 16);
        qfl[kk][0] = *(const uint32_t*)(smem + OFF_KLO + base);
        qfl[kk][1] = *(const uint32_t*)(smem + OFF_KLO + base + 8 * KROW);
        qfl[kk][2] = *(const uint32_t*)(smem + OFF_KLO + base + 16);
        qfl[kk][3] = *(const uint32_t*)(smem + OFF_KLO + base + 8 * KROW + 16);
    }
    __syncthreads();

    const unsigned* mrow0 = g_maskbits + (long long)qrow0 * 64;
    const unsigned* mrow1 = mrow0 + 8 * 64;

    // ================ phase 1: row sums ================
    float lsum0 = 0.f, lsum1 = 0.f;
    for (int kt = 0; kt < NKT; ++kt) {
        load_k_tiles(smem, bh, kt, tid);
        __syncthreads();
        unsigned mw0[4], mw1[4];
        #pragma unroll
        for (int qd = 0; qd < 4; ++qd) { mw0[qd] = mrow0[kt * 4 + qd]; mw1[qd] = mrow1[kt * 4 + qd]; }
        #pragma unroll
        for (int nb = 0; nb < 16; ++nb) {
            float c[4] = {0.f, 0.f, 0.f, 0.f};
            #pragma unroll
            for (int kk = 0; kk < 4; ++kk) {
                int kb = (nb * 8 + gid) * KROW + (kk * 16 + 2 * tig) * 2;
                uint32_t bh0 = *(const uint32_t*)(smem + OFF_KHI + kb);
                uint32_t bh1 = *(const uint32_t*)(smem + OFF_KHI + kb + 16);
                uint32_t bl0 = *(const uint32_t*)(smem + OFF_KLO + kb);
                uint32_t bl1 = *(const uint32_t*)(smem + OFF_KLO + kb + 16);
                mma16816(c, qfh[kk], bh0, bh1);
                mma16816(c, qfh[kk], bl0, bl1);
                mma16816(c, qfl[kk], bh0, bh1);
            }
            int bit = (nb & 3) * 8 + 2 * tig;
            unsigned w0 = mw0[nb >> 2], w1 = mw1[nb >> 2];
            if ((w0 >> bit) & 1u)       lsum0 += __expf(c[0] * 0.125f);
            if ((w0 >> (bit + 1)) & 1u) lsum0 += __expf(c[1] * 0.125f);
            if ((w1 >> bit) & 1u)       lsum1 += __expf(c[2] * 0.125f);
            if ((w1 >> (bit + 1)) & 1u) lsum1 += __expf(c[3] * 0.125f);
        }
        __syncthreads();
    }
    // quad reduce (lanes sharing the same rows differ only in bits 0..1)
    lsum0 += __shfl_xor_sync(0xffffffffu, lsum0, 1);
    lsum0 += __shfl_xor_sync(0xffffffffu, lsum0, 2);
    lsum1 += __shfl_xor_sync(0xffffffffu, lsum1, 1);
    lsum1 += __shfl_xor_sync(0xffffffffu, lsum1, 2);
    float rinv0 = (lsum0 > 0.f) ? 1.f / lsum0 : 0.f;
    float rinv1 = (lsum1 > 0.f) ? 1.f / lsum1 : 0.f;

    // ================ phase 2: attn write + PV ================
    float o[8][4];
    #pragma unroll
    for (int nd = 0; nd < 8; ++nd)
        #pragma unroll
        for (int j = 0; j < 4; ++j) o[nd][j] = 0.f;

    for (int kt = 0; kt < NKT; ++kt) {
        load_k_tiles(smem, bh, kt, tid);
        load_v_tiles(smem, bh, kt, tid);
        __syncthreads();
        unsigned mw0[4], mw1[4];
        #pragma unroll
        for (int qd = 0; qd < 4; ++qd) { mw0[qd] = mrow0[kt * 4 + qd]; mw1[qd] = mrow1[kt * 4 + qd]; }

        uint32_t pkH[16][2], pkL[16][2];
        float* arow0 = attn ? attn + ((long long)bh * Sc + qrow0) * Sc + kt * 128 : (float*)0;

        #pragma unroll
        for (int nb = 0; nb < 16; ++nb) {
            float c[4] = {0.f, 0.f, 0.f, 0.f};
            #pragma unroll
            for (int kk = 0; kk < 4; ++kk) {
                int kb = (nb * 8 + gid) * KROW + (kk * 16 + 2 * tig) * 2;
                uint32_t bh0 = *(const uint32_t*)(smem + OFF_KHI + kb);
                uint32_t bh1 = *(const uint32_t*)(smem + OFF_KHI + kb + 16);
                uint32_t bl0 = *(const uint32_t*)(smem + OFF_KLO + kb);
                uint32_t bl1 = *(const uint32_t*)(smem + OFF_KLO + kb + 16);
                mma16816(c, qfh[kk], bh0, bh1);
                mma16816(c, qfh[kk], bl0, bl1);
                mma16816(c, qfl[kk], bh0, bh1);
            }
            int bit = (nb & 3) * 8 + 2 * tig;
            unsigned w0 = mw0[nb >> 2], w1 = mw1[nb >> 2];
            float p0 = ((w0 >> bit) & 1u)       ? __expf(c[0] * 0.125f) * rinv0 : 0.f;
            float p1 = ((w0 >> (bit + 1)) & 1u) ? __expf(c[1] * 0.125f) * rinv0 : 0.f;
            float p2 = ((w1 >> bit) & 1u)       ? __expf(c[2] * 0.125f) * rinv1 : 0.f;
            float p3 = ((w1 >> (bit + 1)) & 1u) ? __expf(c[3] * 0.125f) * rinv1 : 0.f;
            if (arow0) {
                int cc = nb * 8 + 2 * tig;
                *(float2*)(arow0 + cc)           = make_float2(p0, p1);
                *(float2*)(arow0 + 8 * Sc + cc)  = make_float2(p2, p3);
            }
            // bf16 hi/lo split, packed as A-fragments for PV
            float h0 = __bfloat162float(__float2bfloat16(p0));
            float h1 = __bfloat162float(__float2bfloat16(p1));
            float h2 = __bfloat162float(__float2bfloat16(p2));
            float h3 = __bfloat162float(__float2bfloat16(p3));
            pkH[nb][0] = pk2(h0, h1);
            pkH[nb][1] = pk2(h2, h3);
            pkL[nb][0] = pk2(p0 - h0, p1 - h1);
            pkL[nb][1] = pk2(p2 - h2, p3 - h3);
        }

        // PV: O += P * V   (C->A fragment identity; V^T tiles give B frags)
        #pragma unroll
        for (int kc = 0; kc < 8; ++kc) {
            uint32_t aH[4] = { pkH[2 * kc][0], pkH[2 * kc][1], pkH[2 * kc + 1][0], pkH[2 * kc + 1][1] };
            uint32_t aL[4] = { pkL[2 * kc][0], pkL[2 * kc][1], pkL[2 * kc + 1][0], pkL[2 * kc + 1][1] };
            #pragma unroll
            for (int nd = 0; nd < 8; ++nd) {
                int vb = (nd * 8 + gid) * VROW + (kc * 16 + 2 * tig) * 2;
                uint32_t bh0 = *(const uint32_t*)(smem + OFF_VHI + vb);
                uint32_t bh1 = *(const uint32_t*)(smem + OFF_VHI + vb + 16);
                uint32_t bl0 = *(const uint32_t*)(smem + OFF_VLO + vb);
                uint32_t bl1 = *(const uint32_t*)(smem + OFF_VLO + vb + 16);
                mma16816(o[nd], aH, bh0, bh1);
                mma16816(o[nd], aH, bl0, bl1);
                mma16816(o[nd], aL, bh0, bh1);
            }
        }
        __syncthreads();
    }

    // ================ write O ================
    {
        float* orow = out + ((long long)bh * Sc + qrow0) * Dc;
        #pragma unroll
        for (int nd = 0; nd < 8; ++nd) {
            int cc = nd * 8 + 2 * tig;
            *(float2*)(orow + cc)            = make_float2(o[nd][0], o[nd][1]);
            *(float2*)(orow + 8 * Dc + cc)   = make_float2(o[nd][2], o[nd][3]);
        }
    }
}

// ---------------- launcher ----------------
extern "C" void kernel_launch(void* const* d_in, const int* in_sizes, int n_in,
                              void* d_out, int out_size) {
    const float* q = (const float*)d_in[0];
    const float* k = (const float*)d_in[1];
    const float* v = (const float*)d_in[2];
    const int*   m = (const int*)d_in[3];
    float* out  = (float*)d_out;
    float* attn = ((long long)out_size >= OUT_ELEMS + ATTN_ELEMS) ? out + OUT_ELEMS : (float*)0;

    cudaFuncSetAttribute(attn_main_kernel,
                         cudaFuncAttributeMaxDynamicSharedMemorySize, SMEM_BYTES);

    conv_qk_kernel<<<QKD / 256, 256>>>(q, k);
    conv_v_kernel<<<BHc * (Sc / 64), 256>>>(v);
    pack_mask_kernel<<<MASKW / 256, 256>>>(m);
    attn_main_kernel<<<dim3(NKT, BHc), 256, SMEM_BYTES>>>(out, attn);
}